// round 13
// baseline (speedup 1.0000x reference)
#include <cuda_runtime.h>
#include <cuda_bf16.h>
#include <cstdint>

#define DIM 256
#define MAXS 20000
#define S_PAD 20096   // 157 * 128 GEMM padding; tail rows stay zero

// ---------------- scratch (__device__ globals; zero-initialized at load) ----
__device__ __nv_bfloat16 g_pooled_hi[(size_t)S_PAD * DIM];
__device__ __nv_bfloat16 g_pooled_lo[(size_t)S_PAD * DIM];
__device__ float g_gsum[MAXS];
__device__ __nv_bfloat16 g_wmT_hi[DIM * DIM];   // Wm^T: [n][k]
__device__ __nv_bfloat16 g_wmT_lo[DIM * DIM];
__device__ int g_seg_start[MAXS + 1];
__device__ unsigned int g_ctr;                   // work-stealing counter

#define LOG2E 1.4426950408889634f

// ---------------- helpers ---------------------------------------------------
__device__ __forceinline__ uint32_t smem_u32(const void* p) {
    uint32_t a;
    asm("{ .reg .u64 t; cvta.to.shared.u64 t, %1; cvt.u32.u64 %0, t; }"
        : "=r"(a) : "l"(p));
    return a;
}
__device__ __forceinline__ void ldm_x4(uint32_t* r, uint32_t addr) {
    asm volatile("ldmatrix.sync.aligned.m8n8.x4.shared.b16 {%0,%1,%2,%3}, [%4];"
                 : "=r"(r[0]), "=r"(r[1]), "=r"(r[2]), "=r"(r[3]) : "r"(addr));
}
__device__ __forceinline__ void mma_bf16(float* c, const uint32_t* a, const uint32_t* b) {
    asm volatile("mma.sync.aligned.m16n8k16.row.col.f32.bf16.bf16.f32 "
                 "{%0,%1,%2,%3}, {%4,%5,%6,%7}, {%8,%9}, {%0,%1,%2,%3};"
                 : "+f"(c[0]), "+f"(c[1]), "+f"(c[2]), "+f"(c[3])
                 : "r"(a[0]), "r"(a[1]), "r"(a[2]), "r"(a[3]), "r"(b[0]), "r"(b[1]));
}
__device__ __forceinline__ uint32_t pack_bf2(float a, float b) {
    __nv_bfloat162 h = __floats2bfloat162_rn(a, b);
    return *(uint32_t*)&h;
}
__device__ __forceinline__ void pf_l2(const void* p) {
    asm volatile("prefetch.global.L2 [%0];" :: "l"(p));
}
// w^p * e^g = exp2(p*log2(w) + g*log2e)  -- 2 MUFU instead of 3
__device__ __forceinline__ float wexp(float wt, float pval, float g) {
    return exp2f(fmaf(pval, __log2f(wt), g * LOG2E));
}

// ---------------------------------------------------------------------------
// Kernel 0: segment boundary scatter + Wm^T bf16 hi/lo prep + counter reset.
// The reset is stream-ordered before seg_pool, so every launch/replay is
// deterministic and graph-capturable.
// ---------------------------------------------------------------------------
__global__ void __launch_bounds__(256) bounds_prep_kernel(
    const int* __restrict__ index, const float* __restrict__ Wm, int N, int S)
{
    if (blockIdx.x == 0 && threadIdx.x == 0) g_ctr = 0;  // reset each replay
    int i0 = (blockIdx.x * 256 + threadIdx.x) * 4;
    if (i0 < N) {
        int prev = (i0 == 0) ? -1 : __ldg(index + i0 - 1);
        #pragma unroll
        for (int j = 0; j < 4; j++) {
            int i = i0 + j;
            if (i < N) {
                int b = __ldg(index + i);
                for (int s = prev + 1; s <= b; s++) g_seg_start[s] = i;
                prev = b;
                if (i == N - 1)
                    for (int s = b + 1; s <= S; s++) g_seg_start[s] = N;
            }
        }
    }
    if (blockIdx.x < DIM) {
        int k = blockIdx.x, n = threadIdx.x;
        float v = Wm[k * DIM + n];
        __nv_bfloat16 hi = __float2bfloat16(v);
        g_wmT_hi[n * DIM + k] = hi;
        g_wmT_lo[n * DIM + k] = __float2bfloat16(v - __bfloat162float(hi));
    }
}

// ---------------------------------------------------------------------------
// Kernel A: persistent-warp work-stealing softmax pooling.
// Fixed grid (~2 blocks/SM, all resident). Each WARP grabs the next segment
// from a global counter (one single-lane atomic per segment, ~8 segs/warp),
// eliminating the block-exit convoy from segment-size variance (E[max of 8]
// ~ 33 rows vs mean 25 => ~30% idle with static warp-per-segment mapping).
// Per-segment body identical to R7 best: unroll-4, distance-8 L2 prefetch.
// Softmax max-subtraction cancels algebraically (gate ~ N(0,1), exp safe).
// Warps exit independently when the counter exceeds S -> no deadlock.
// ---------------------------------------------------------------------------
__global__ void __launch_bounds__(256) seg_pool_kernel(
    const float* __restrict__ x,
    const float* __restrict__ weights,
    const float* __restrict__ Wg,
    const float* __restrict__ pptr,
    int N, int S)
{
    int lane = threadIdx.x & 31;

    const float4* Wg4 = (const float4*)Wg;
    float4 wg0 = __ldg(Wg4 + lane);
    float4 wg1 = __ldg(Wg4 + lane + 32);
    float pval = pptr[0];

    int pf_row_off = lane >> 3;          // 0..3
    int pf_col     = (lane & 7) * 32;    // float offset of a 128B line

    while (true) {
        int s = 0;
        if (lane == 0) s = (int)atomicAdd(&g_ctr, 1u);
        s = __shfl_sync(0xFFFFFFFFu, s, 0);
        if (s >= S) break;

        int n0 = g_seg_start[s];
        int cnt = g_seg_start[s + 1] - n0;
        size_t po = (size_t)s * DIM;

        if (cnt == 0) {
            *(uint2*)(g_pooled_hi + po + 4 * lane)       = make_uint2(0, 0);
            *(uint2*)(g_pooled_hi + po + 128 + 4 * lane) = make_uint2(0, 0);
            *(uint2*)(g_pooled_lo + po + 4 * lane)       = make_uint2(0, 0);
            *(uint2*)(g_pooled_lo + po + 128 + 4 * lane) = make_uint2(0, 0);
            if (lane == 0) g_gsum[s] = 0.f;
            continue;
        }

        float acc[8] = {};
        float denom = 0.f;

        int i = 0;
        for (; i + 4 <= cnt; i += 4) {
            const float4* x0 = (const float4*)(x + (size_t)(n0 + i) * DIM);
            const float4* x1 = (const float4*)(x + (size_t)(n0 + i + 1) * DIM);
            const float4* x2 = (const float4*)(x + (size_t)(n0 + i + 2) * DIM);
            const float4* x3 = (const float4*)(x + (size_t)(n0 + i + 3) * DIM);
            float4 a0 = x0[lane], a1 = x0[lane + 32];
            float4 b0 = x1[lane], b1 = x1[lane + 32];
            float4 c0 = x2[lane], c1 = x2[lane + 32];
            float4 d0 = x3[lane], d1 = x3[lane + 32];
            float wt0 = __ldg(weights + n0 + i);
            float wt1 = __ldg(weights + n0 + i + 1);
            float wt2 = __ldg(weights + n0 + i + 2);
            float wt3 = __ldg(weights + n0 + i + 3);

            // prefetch 4 rows, 8 ahead (2 iterations); clamp only to N
            int pr = n0 + i + 8 + pf_row_off;
            pr = (pr < N) ? pr : (N - 1);
            pf_l2(x + (size_t)pr * DIM + pf_col);

            float g0 = a0.x * wg0.x + a0.y * wg0.y + a0.z * wg0.z + a0.w * wg0.w
                     + a1.x * wg1.x + a1.y * wg1.y + a1.z * wg1.z + a1.w * wg1.w;
            float g1 = b0.x * wg0.x + b0.y * wg0.y + b0.z * wg0.z + b0.w * wg0.w
                     + b1.x * wg1.x + b1.y * wg1.y + b1.z * wg1.z + b1.w * wg1.w;
            float g2 = c0.x * wg0.x + c0.y * wg0.y + c0.z * wg0.z + c0.w * wg0.w
                     + c1.x * wg1.x + c1.y * wg1.y + c1.z * wg1.z + c1.w * wg1.w;
            float g3 = d0.x * wg0.x + d0.y * wg0.y + d0.z * wg0.z + d0.w * wg0.w
                     + d1.x * wg1.x + d1.y * wg1.y + d1.z * wg1.z + d1.w * wg1.w;
            #pragma unroll
            for (int o = 16; o; o >>= 1) {
                g0 += __shfl_xor_sync(0xFFFFFFFFu, g0, o);
                g1 += __shfl_xor_sync(0xFFFFFFFFu, g1, o);
                g2 += __shfl_xor_sync(0xFFFFFFFFu, g2, o);
                g3 += __shfl_xor_sync(0xFFFFFFFFu, g3, o);
            }
            float gv0 = wexp(wt0, pval, g0);
            float gv1 = wexp(wt1, pval, g1);
            float gv2 = wexp(wt2, pval, g2);
            float gv3 = wexp(wt3, pval, g3);
            denom += (gv0 + gv1) + (gv2 + gv3);
            acc[0] += gv0 * a0.x + gv1 * b0.x + gv2 * c0.x + gv3 * d0.x;
            acc[1] += gv0 * a0.y + gv1 * b0.y + gv2 * c0.y + gv3 * d0.y;
            acc[2] += gv0 * a0.z + gv1 * b0.z + gv2 * c0.z + gv3 * d0.z;
            acc[3] += gv0 * a0.w + gv1 * b0.w + gv2 * c0.w + gv3 * d0.w;
            acc[4] += gv0 * a1.x + gv1 * b1.x + gv2 * c1.x + gv3 * d1.x;
            acc[5] += gv0 * a1.y + gv1 * b1.y + gv2 * c1.y + gv3 * d1.y;
            acc[6] += gv0 * a1.z + gv1 * b1.z + gv2 * c1.z + gv3 * d1.z;
            acc[7] += gv0 * a1.w + gv1 * b1.w + gv2 * c1.w + gv3 * d1.w;
        }
        for (; i < cnt; i++) {
            const float4* xr = (const float4*)(x + (size_t)(n0 + i) * DIM);
            float4 a0 = xr[lane], a1 = xr[lane + 32];
            float wt = __ldg(weights + n0 + i);
            float g = a0.x * wg0.x + a0.y * wg0.y + a0.z * wg0.z + a0.w * wg0.w
                    + a1.x * wg1.x + a1.y * wg1.y + a1.z * wg1.z + a1.w * wg1.w;
            #pragma unroll
            for (int o = 16; o; o >>= 1) g += __shfl_xor_sync(0xFFFFFFFFu, g, o);
            float gv = wexp(wt, pval, g);
            denom += gv;
            acc[0] += gv * a0.x; acc[1] += gv * a0.y;
            acc[2] += gv * a0.z; acc[3] += gv * a0.w;
            acc[4] += gv * a1.x; acc[5] += gv * a1.y;
            acc[6] += gv * a1.z; acc[7] += gv * a1.w;
        }

        float scale = 1.f / (denom + 1e-10f);
        float v[8], hi[8], lo[8];
        #pragma unroll
        for (int j = 0; j < 8; j++) {
            v[j] = acc[j] * scale;
            hi[j] = __bfloat162float(__float2bfloat16(v[j]));
            lo[j] = v[j] - hi[j];
        }
        *(uint2*)(g_pooled_hi + po + 4 * lane) =
            make_uint2(pack_bf2(hi[0], hi[1]), pack_bf2(hi[2], hi[3]));
        *(uint2*)(g_pooled_hi + po + 128 + 4 * lane) =
            make_uint2(pack_bf2(hi[4], hi[5]), pack_bf2(hi[6], hi[7]));
        *(uint2*)(g_pooled_lo + po + 4 * lane) =
            make_uint2(pack_bf2(lo[0], lo[1]), pack_bf2(lo[2], lo[3]));
        *(uint2*)(g_pooled_lo + po + 128 + 4 * lane) =
            make_uint2(pack_bf2(lo[4], lo[5]), pack_bf2(lo[6], lo[7]));
        if (lane == 0) g_gsum[s] = denom * scale;
    }
}

// ---------------------------------------------------------------------------
// Kernel B: mma.sync bf16 split GEMM — static-smem version (measured good).
// out[S,256] = pooled@Wm + gsum*bm ≈ (Ahi Bhi + Ahi Blo + Alo Bhi), fp32 acc.
// ---------------------------------------------------------------------------
#define KPAD 40

__global__ void __launch_bounds__(256) out_gemm_mma_kernel(
    const float* __restrict__ bm, float* __restrict__ out, int S)
{
    __shared__ __nv_bfloat16 sAh[128 * KPAD];
    __shared__ __nv_bfloat16 sAl[128 * KPAD];
    __shared__ __nv_bfloat16 sBh[128 * KPAD];
    __shared__ __nv_bfloat16 sBl[128 * KPAD];

    int tid = threadIdx.x, wid = tid >> 5, lane = tid & 31;
    int wm = wid & 3, wn = wid >> 2;
    int m0 = blockIdx.x * 128;
    int nh = blockIdx.y * 128;

    uint32_t uAh = smem_u32(sAh), uAl = smem_u32(sAl);
    uint32_t uBh = smem_u32(sBh), uBl = smem_u32(sBl);

    uint32_t a_row = wm * 32 + (lane & 15);
    uint32_t a_k8  = (lane >> 4) * 8;
    uint32_t b_row = wn * 64 + (lane >> 4) * 8 + (lane & 7);
    uint32_t b_k8  = ((lane >> 3) & 1) * 8;

    float acc[2][8][4];
    #pragma unroll
    for (int i = 0; i < 2; i++)
        #pragma unroll
        for (int j = 0; j < 8; j++)
            #pragma unroll
            for (int q = 0; q < 4; q++) acc[i][j][q] = 0.f;

    int r_ld[2], q_ld[2];
    #pragma unroll
    for (int i = 0; i < 2; i++) {
        int it = tid * 2 + i;
        r_ld[i] = it >> 2;
        q_ld[i] = it & 3;
    }

    for (int c = 0; c < 8; c++) {
        int k0 = c * 32;
        #pragma unroll
        for (int i = 0; i < 2; i++) {
            int r = r_ld[i], q = q_ld[i];
            uint32_t doff = (uint32_t)(r * KPAD + q * 8);
            size_t asrc = (size_t)(m0 + r) * DIM + k0 + q * 8;
            size_t bsrc = (size_t)(nh + r) * DIM + k0 + q * 8;
            *(uint4*)(sAh + doff) = *(const uint4*)(g_pooled_hi + asrc);
            *(uint4*)(sAl + doff) = *(const uint4*)(g_pooled_lo + asrc);
            *(uint4*)(sBh + doff) = *(const uint4*)(g_wmT_hi + bsrc);
            *(uint4*)(sBl + doff) = *(const uint4*)(g_wmT_lo + bsrc);
        }
        __syncthreads();

        #pragma unroll
        for (int kk = 0; kk < 32; kk += 16) {
            uint32_t ah[2][4], al[2][4];
            #pragma unroll
            for (int mt = 0; mt < 2; mt++) {
                uint32_t off = ((a_row + mt * 16) * KPAD + kk + a_k8) * 2;
                ldm_x4(ah[mt], uAh + off);
                ldm_x4(al[mt], uAl + off);
            }
            uint32_t bh[4][4], bl[4][4];
            #pragma unroll
            for (int nt = 0; nt < 4; nt++) {
                uint32_t off = ((b_row + nt * 16) * KPAD + kk + b_k8) * 2;
                ldm_x4(bh[nt], uBh + off);
                ldm_x4(bl[nt], uBl + off);
            }
            #pragma unroll
            for (int mt = 0; mt < 2; mt++)
                #pragma unroll
                for (int nt = 0; nt < 8; nt++) {
                    const uint32_t* pbh = &bh[nt >> 1][(nt & 1) * 2];
                    const uint32_t* pbl = &bl[nt >> 1][(nt & 1) * 2];
                    mma_bf16(acc[mt][nt], ah[mt], pbh);
                    mma_bf16(acc[mt][nt], ah[mt], pbl);
                    mma_bf16(acc[mt][nt], al[mt], pbh);
                }
        }
        __syncthreads();
    }

    #pragma unroll
    for (int mt = 0; mt < 2; mt++) {
        int r0 = m0 + wm * 32 + mt * 16 + (lane >> 2);
        int r1 = r0 + 8;
        float gs0 = (r0 < S) ? g_gsum[r0] : 0.f;
        float gs1 = (r1 < S) ? g_gsum[r1] : 0.f;
        #pragma unroll
        for (int nt = 0; nt < 8; nt++) {
            int col = nh + wn * 64 + nt * 8 + (lane & 3) * 2;
            float2 bm2 = *(const float2*)(bm + col);
            if (r0 < S) {
                float2 v = make_float2(acc[mt][nt][0] + gs0 * bm2.x,
                                       acc[mt][nt][1] + gs0 * bm2.y);
                *(float2*)(out + (size_t)r0 * DIM + col) = v;
            }
            if (r1 < S) {
                float2 v = make_float2(acc[mt][nt][2] + gs1 * bm2.x,
                                       acc[mt][nt][3] + gs1 * bm2.y);
                *(float2*)(out + (size_t)r1 * DIM + col) = v;
            }
        }
    }
}

// ---------------------------------------------------------------------------
// Launch. Inputs: x, weights, Wg, bg, Wm, bm, p, index, num_segments
// bg cancels in the segment softmax.
// ---------------------------------------------------------------------------
extern "C" void kernel_launch(void* const* d_in, const int* in_sizes, int n_in,
                              void* d_out, int out_size) {
    const float* x       = (const float*)d_in[0];
    const float* weights = (const float*)d_in[1];
    const float* Wg      = (const float*)d_in[2];
    const float* Wm      = (const float*)d_in[4];
    const float* bm      = (const float*)d_in[5];
    const float* p       = (const float*)d_in[6];
    const int*   index   = (const int*)d_in[7];

    int N = in_sizes[0] / DIM;
    int S = out_size / DIM;
    float* out = (float*)d_out;

    int bblocks = (N + 1023) / 1024;
    if (bblocks < DIM) bblocks = DIM;
    bounds_prep_kernel<<<bblocks, 256>>>(index, Wm, N, S);

    seg_pool_kernel<<<304, 256>>>(x, weights, Wg, p, N, S);  // persistent, 2/SM

    dim3 grid((S + 127) / 128, 2);
    out_gemm_mma_kernel<<<grid, 256>>>(bm, out, S);
}

// round 14
// speedup vs baseline: 1.0653x; 1.0653x over previous
#include <cuda_runtime.h>
#include <cuda_bf16.h>
#include <cstdint>

#define DIM 256
#define MAXS 20000
#define S_PAD 20096   // 157 * 128 GEMM padding; tail rows stay zero

// ---------------- scratch (__device__ globals; zero-initialized at load) ----
__device__ __nv_bfloat16 g_pooled_hi[(size_t)S_PAD * DIM];
__device__ __nv_bfloat16 g_pooled_lo[(size_t)S_PAD * DIM];
__device__ float g_gsum[MAXS];
__device__ __nv_bfloat16 g_wmT_hi[DIM * DIM];   // Wm^T: [n][k]
__device__ __nv_bfloat16 g_wmT_lo[DIM * DIM];
__device__ int g_seg_start[MAXS + 1];

#define LOG2E 1.4426950408889634f

// ---------------- helpers ---------------------------------------------------
__device__ __forceinline__ uint32_t smem_u32(const void* p) {
    uint32_t a;
    asm("{ .reg .u64 t; cvta.to.shared.u64 t, %1; cvt.u32.u64 %0, t; }"
        : "=r"(a) : "l"(p));
    return a;
}
__device__ __forceinline__ void ldm_x4(uint32_t* r, uint32_t addr) {
    asm volatile("ldmatrix.sync.aligned.m8n8.x4.shared.b16 {%0,%1,%2,%3}, [%4];"
                 : "=r"(r[0]), "=r"(r[1]), "=r"(r[2]), "=r"(r[3]) : "r"(addr));
}
__device__ __forceinline__ void mma_bf16(float* c, const uint32_t* a, const uint32_t* b) {
    asm volatile("mma.sync.aligned.m16n8k16.row.col.f32.bf16.bf16.f32 "
                 "{%0,%1,%2,%3}, {%4,%5,%6,%7}, {%8,%9}, {%0,%1,%2,%3};"
                 : "+f"(c[0]), "+f"(c[1]), "+f"(c[2]), "+f"(c[3])
                 : "r"(a[0]), "r"(a[1]), "r"(a[2]), "r"(a[3]), "r"(b[0]), "r"(b[1]));
}
__device__ __forceinline__ uint32_t pack_bf2(float a, float b) {
    __nv_bfloat162 h = __floats2bfloat162_rn(a, b);
    return *(uint32_t*)&h;
}
__device__ __forceinline__ void pf_l2(const void* p) {
    asm volatile("prefetch.global.L2 [%0];" :: "l"(p));
}
// w^p * e^g = exp2(p*log2(w) + g*log2e)  -- 2 MUFU instead of 3
__device__ __forceinline__ float wexp(float wt, float pval, float g) {
    return exp2f(fmaf(pval, __log2f(wt), g * LOG2E));
}

// ---------------------------------------------------------------------------
// Kernel 0: segment boundary scatter (4 entries/thread, scalar; measured
// 7.4us) + Wm^T bf16 hi/lo prep.
// ---------------------------------------------------------------------------
__global__ void __launch_bounds__(256) bounds_prep_kernel(
    const int* __restrict__ index, const float* __restrict__ Wm, int N, int S)
{
    int i0 = (blockIdx.x * 256 + threadIdx.x) * 4;
    if (i0 < N) {
        int prev = (i0 == 0) ? -1 : __ldg(index + i0 - 1);
        #pragma unroll
        for (int j = 0; j < 4; j++) {
            int i = i0 + j;
            if (i < N) {
                int b = __ldg(index + i);
                for (int s = prev + 1; s <= b; s++) g_seg_start[s] = i;
                prev = b;
                if (i == N - 1)
                    for (int s = b + 1; s <= S; s++) g_seg_start[s] = N;
            }
        }
    }
    if (blockIdx.x < DIM) {
        int k = blockIdx.x, n = threadIdx.x;
        float v = Wm[k * DIM + n];
        __nv_bfloat16 hi = __float2bfloat16(v);
        g_wmT_hi[n * DIM + k] = hi;
        g_wmT_lo[n * DIM + k] = __float2bfloat16(v - __bfloat162float(hi));
    }
}

// ---------------------------------------------------------------------------
// Kernel A: warp-per-4-CONSECUTIVE-segments single-pass softmax pooling.
// Consecutive segments own contiguous x rows, so the distance-8 L2 prefetch
// stream (which deliberately overshoots each segment's end into the next
// rows) stays primed ACROSS segment boundaries: the DRAM cold-start (~2
// iterations of fully exposed 577-cyc latency) is paid once per ~100 rows
// instead of once per ~25. Also halves relative per-warp work variance.
// Body per segment identical to the measured-best R7: unroll-4, distance-8
// prefetch, wexp. No smem, no block syncs, no atomics.
// Softmax max-subtraction cancels algebraically (gate ~ N(0,1), exp safe).
// ---------------------------------------------------------------------------
#define SEGS_PER_WARP 4

__global__ void __launch_bounds__(256) seg_pool_kernel(
    const float* __restrict__ x,
    const float* __restrict__ weights,
    const float* __restrict__ Wg,
    const float* __restrict__ pptr,
    int N, int S)
{
    int w = threadIdx.x >> 5, lane = threadIdx.x & 31;
    int s0 = (blockIdx.x * 8 + w) * SEGS_PER_WARP;
    if (s0 >= S) return;

    const float4* Wg4 = (const float4*)Wg;
    float4 wg0 = __ldg(Wg4 + lane);
    float4 wg1 = __ldg(Wg4 + lane + 32);
    float pval = pptr[0];

    int pf_row_off = lane >> 3;          // 0..3
    int pf_col     = (lane & 7) * 32;    // float offset of a 128B line

    for (int q = 0; q < SEGS_PER_WARP; q++) {
        int s = s0 + q;
        if (s >= S) break;

        int n0 = g_seg_start[s];
        int cnt = g_seg_start[s + 1] - n0;
        size_t po = (size_t)s * DIM;

        if (cnt == 0) {
            *(uint2*)(g_pooled_hi + po + 4 * lane)       = make_uint2(0, 0);
            *(uint2*)(g_pooled_hi + po + 128 + 4 * lane) = make_uint2(0, 0);
            *(uint2*)(g_pooled_lo + po + 4 * lane)       = make_uint2(0, 0);
            *(uint2*)(g_pooled_lo + po + 128 + 4 * lane) = make_uint2(0, 0);
            if (lane == 0) g_gsum[s] = 0.f;
            continue;
        }

        float acc[8] = {};
        float denom = 0.f;

        int i = 0;
        for (; i + 4 <= cnt; i += 4) {
            const float4* x0 = (const float4*)(x + (size_t)(n0 + i) * DIM);
            const float4* x1 = (const float4*)(x + (size_t)(n0 + i + 1) * DIM);
            const float4* x2 = (const float4*)(x + (size_t)(n0 + i + 2) * DIM);
            const float4* x3 = (const float4*)(x + (size_t)(n0 + i + 3) * DIM);
            float4 a0 = x0[lane], a1 = x0[lane + 32];
            float4 b0 = x1[lane], b1 = x1[lane + 32];
            float4 c0 = x2[lane], c1 = x2[lane + 32];
            float4 d0 = x3[lane], d1 = x3[lane + 32];
            float wt0 = __ldg(weights + n0 + i);
            float wt1 = __ldg(weights + n0 + i + 1);
            float wt2 = __ldg(weights + n0 + i + 2);
            float wt3 = __ldg(weights + n0 + i + 3);

            // prefetch 4 rows, 8 ahead (2 iterations); clamp only to N.
            // overshoot past this segment's end lands on the warp's own NEXT
            // consecutive segment -> cold-start amortized across 4 segments.
            int pr = n0 + i + 8 + pf_row_off;
            pr = (pr < N) ? pr : (N - 1);
            pf_l2(x + (size_t)pr * DIM + pf_col);

            float g0 = a0.x * wg0.x + a0.y * wg0.y + a0.z * wg0.z + a0.w * wg0.w
                     + a1.x * wg1.x + a1.y * wg1.y + a1.z * wg1.z + a1.w * wg1.w;
            float g1 = b0.x * wg0.x + b0.y * wg0.y + b0.z * wg0.z + b0.w * wg0.w
                     + b1.x * wg1.x + b1.y * wg1.y + b1.z * wg1.z + b1.w * wg1.w;
            float g2 = c0.x * wg0.x + c0.y * wg0.y + c0.z * wg0.z + c0.w * wg0.w
                     + c1.x * wg1.x + c1.y * wg1.y + c1.z * wg1.z + c1.w * wg1.w;
            float g3 = d0.x * wg0.x + d0.y * wg0.y + d0.z * wg0.z + d0.w * wg0.w
                     + d1.x * wg1.x + d1.y * wg1.y + d1.z * wg1.z + d1.w * wg1.w;
            #pragma unroll
            for (int o = 16; o; o >>= 1) {
                g0 += __shfl_xor_sync(0xFFFFFFFFu, g0, o);
                g1 += __shfl_xor_sync(0xFFFFFFFFu, g1, o);
                g2 += __shfl_xor_sync(0xFFFFFFFFu, g2, o);
                g3 += __shfl_xor_sync(0xFFFFFFFFu, g3, o);
            }
            float gv0 = wexp(wt0, pval, g0);
            float gv1 = wexp(wt1, pval, g1);
            float gv2 = wexp(wt2, pval, g2);
            float gv3 = wexp(wt3, pval, g3);
            denom += (gv0 + gv1) + (gv2 + gv3);
            acc[0] += gv0 * a0.x + gv1 * b0.x + gv2 * c0.x + gv3 * d0.x;
            acc[1] += gv0 * a0.y + gv1 * b0.y + gv2 * c0.y + gv3 * d0.y;
            acc[2] += gv0 * a0.z + gv1 * b0.z + gv2 * c0.z + gv3 * d0.z;
            acc[3] += gv0 * a0.w + gv1 * b0.w + gv2 * c0.w + gv3 * d0.w;
            acc[4] += gv0 * a1.x + gv1 * b1.x + gv2 * c1.x + gv3 * d1.x;
            acc[5] += gv0 * a1.y + gv1 * b1.y + gv2 * c1.y + gv3 * d1.y;
            acc[6] += gv0 * a1.z + gv1 * b1.z + gv2 * c1.z + gv3 * d1.z;
            acc[7] += gv0 * a1.w + gv1 * b1.w + gv2 * c1.w + gv3 * d1.w;
        }
        for (; i < cnt; i++) {
            const float4* xr = (const float4*)(x + (size_t)(n0 + i) * DIM);
            float4 a0 = xr[lane], a1 = xr[lane + 32];
            float wt = __ldg(weights + n0 + i);
            float g = a0.x * wg0.x + a0.y * wg0.y + a0.z * wg0.z + a0.w * wg0.w
                    + a1.x * wg1.x + a1.y * wg1.y + a1.z * wg1.z + a1.w * wg1.w;
            #pragma unroll
            for (int o = 16; o; o >>= 1) g += __shfl_xor_sync(0xFFFFFFFFu, g, o);
            float gv = wexp(wt, pval, g);
            denom += gv;
            acc[0] += gv * a0.x; acc[1] += gv * a0.y;
            acc[2] += gv * a0.z; acc[3] += gv * a0.w;
            acc[4] += gv * a1.x; acc[5] += gv * a1.y;
            acc[6] += gv * a1.z; acc[7] += gv * a1.w;
        }

        float scale = 1.f / (denom + 1e-10f);
        float v[8], hi[8], lo[8];
        #pragma unroll
        for (int j = 0; j < 8; j++) {
            v[j] = acc[j] * scale;
            hi[j] = __bfloat162float(__float2bfloat16(v[j]));
            lo[j] = v[j] - hi[j];
        }
        *(uint2*)(g_pooled_hi + po + 4 * lane) =
            make_uint2(pack_bf2(hi[0], hi[1]), pack_bf2(hi[2], hi[3]));
        *(uint2*)(g_pooled_hi + po + 128 + 4 * lane) =
            make_uint2(pack_bf2(hi[4], hi[5]), pack_bf2(hi[6], hi[7]));
        *(uint2*)(g_pooled_lo + po + 4 * lane) =
            make_uint2(pack_bf2(lo[0], lo[1]), pack_bf2(lo[2], lo[3]));
        *(uint2*)(g_pooled_lo + po + 128 + 4 * lane) =
            make_uint2(pack_bf2(lo[4], lo[5]), pack_bf2(lo[6], lo[7]));
        if (lane == 0) g_gsum[s] = denom * scale;
    }
}

// ---------------------------------------------------------------------------
// Kernel B: mma.sync bf16 split GEMM — static-smem version (measured good).
// out[S,256] = pooled@Wm + gsum*bm ≈ (Ahi Bhi + Ahi Blo + Alo Bhi), fp32 acc.
// ---------------------------------------------------------------------------
#define KPAD 40

__global__ void __launch_bounds__(256) out_gemm_mma_kernel(
    const float* __restrict__ bm, float* __restrict__ out, int S)
{
    __shared__ __nv_bfloat16 sAh[128 * KPAD];
    __shared__ __nv_bfloat16 sAl[128 * KPAD];
    __shared__ __nv_bfloat16 sBh[128 * KPAD];
    __shared__ __nv_bfloat16 sBl[128 * KPAD];

    int tid = threadIdx.x, wid = tid >> 5, lane = tid & 31;
    int wm = wid & 3, wn = wid >> 2;
    int m0 = blockIdx.x * 128;
    int nh = blockIdx.y * 128;

    uint32_t uAh = smem_u32(sAh), uAl = smem_u32(sAl);
    uint32_t uBh = smem_u32(sBh), uBl = smem_u32(sBl);

    uint32_t a_row = wm * 32 + (lane & 15);
    uint32_t a_k8  = (lane >> 4) * 8;
    uint32_t b_row = wn * 64 + (lane >> 4) * 8 + (lane & 7);
    uint32_t b_k8  = ((lane >> 3) & 1) * 8;

    float acc[2][8][4];
    #pragma unroll
    for (int i = 0; i < 2; i++)
        #pragma unroll
        for (int j = 0; j < 8; j++)
            #pragma unroll
            for (int q = 0; q < 4; q++) acc[i][j][q] = 0.f;

    int r_ld[2], q_ld[2];
    #pragma unroll
    for (int i = 0; i < 2; i++) {
        int it = tid * 2 + i;
        r_ld[i] = it >> 2;
        q_ld[i] = it & 3;
    }

    for (int c = 0; c < 8; c++) {
        int k0 = c * 32;
        #pragma unroll
        for (int i = 0; i < 2; i++) {
            int r = r_ld[i], q = q_ld[i];
            uint32_t doff = (uint32_t)(r * KPAD + q * 8);
            size_t asrc = (size_t)(m0 + r) * DIM + k0 + q * 8;
            size_t bsrc = (size_t)(nh + r) * DIM + k0 + q * 8;
            *(uint4*)(sAh + doff) = *(const uint4*)(g_pooled_hi + asrc);
            *(uint4*)(sAl + doff) = *(const uint4*)(g_pooled_lo + asrc);
            *(uint4*)(sBh + doff) = *(const uint4*)(g_wmT_hi + bsrc);
            *(uint4*)(sBl + doff) = *(const uint4*)(g_wmT_lo + bsrc);
        }
        __syncthreads();

        #pragma unroll
        for (int kk = 0; kk < 32; kk += 16) {
            uint32_t ah[2][4], al[2][4];
            #pragma unroll
            for (int mt = 0; mt < 2; mt++) {
                uint32_t off = ((a_row + mt * 16) * KPAD + kk + a_k8) * 2;
                ldm_x4(ah[mt], uAh + off);
                ldm_x4(al[mt], uAl + off);
            }
            uint32_t bh[4][4], bl[4][4];
            #pragma unroll
            for (int nt = 0; nt < 4; nt++) {
                uint32_t off = ((b_row + nt * 16) * KPAD + kk + b_k8) * 2;
                ldm_x4(bh[nt], uBh + off);
                ldm_x4(bl[nt], uBl + off);
            }
            #pragma unroll
            for (int mt = 0; mt < 2; mt++)
                #pragma unroll
                for (int nt = 0; nt < 8; nt++) {
                    const uint32_t* pbh = &bh[nt >> 1][(nt & 1) * 2];
                    const uint32_t* pbl = &bl[nt >> 1][(nt & 1) * 2];
                    mma_bf16(acc[mt][nt], ah[mt], pbh);
                    mma_bf16(acc[mt][nt], ah[mt], pbl);
                    mma_bf16(acc[mt][nt], al[mt], pbh);
                }
        }
        __syncthreads();
    }

    #pragma unroll
    for (int mt = 0; mt < 2; mt++) {
        int r0 = m0 + wm * 32 + mt * 16 + (lane >> 2);
        int r1 = r0 + 8;
        float gs0 = (r0 < S) ? g_gsum[r0] : 0.f;
        float gs1 = (r1 < S) ? g_gsum[r1] : 0.f;
        #pragma unroll
        for (int nt = 0; nt < 8; nt++) {
            int col = nh + wn * 64 + nt * 8 + (lane & 3) * 2;
            float2 bm2 = *(const float2*)(bm + col);
            if (r0 < S) {
                float2 v = make_float2(acc[mt][nt][0] + gs0 * bm2.x,
                                       acc[mt][nt][1] + gs0 * bm2.y);
                *(float2*)(out + (size_t)r0 * DIM + col) = v;
            }
            if (r1 < S) {
                float2 v = make_float2(acc[mt][nt][2] + gs1 * bm2.x,
                                       acc[mt][nt][3] + gs1 * bm2.y);
                *(float2*)(out + (size_t)r1 * DIM + col) = v;
            }
        }
    }
}

// ---------------------------------------------------------------------------
// Launch. Inputs: x, weights, Wg, bg, Wm, bm, p, index, num_segments
// bg cancels in the segment softmax.
// ---------------------------------------------------------------------------
extern "C" void kernel_launch(void* const* d_in, const int* in_sizes, int n_in,
                              void* d_out, int out_size) {
    const float* x       = (const float*)d_in[0];
    const float* weights = (const float*)d_in[1];
    const float* Wg      = (const float*)d_in[2];
    const float* Wm      = (const float*)d_in[4];
    const float* bm      = (const float*)d_in[5];
    const float* p       = (const float*)d_in[6];
    const int*   index   = (const int*)d_in[7];

    int N = in_sizes[0] / DIM;
    int S = out_size / DIM;
    float* out = (float*)d_out;

    int bblocks = (N + 1023) / 1024;
    if (bblocks < DIM) bblocks = DIM;
    bounds_prep_kernel<<<bblocks, 256>>>(index, Wm, N, S);

    int sblocks = (S + 8 * SEGS_PER_WARP - 1) / (8 * SEGS_PER_WARP);
    seg_pool_kernel<<<sblocks, 256>>>(x, weights, Wg, p, N, S);

    dim3 grid((S + 127) / 128, 2);
    out_gemm_mma_kernel<<<grid, 256>>>(bm, out, S);
}

// round 16
// speedup vs baseline: 1.1303x; 1.0611x over previous
#include <cuda_runtime.h>
#include <cuda_bf16.h>
#include <cstdint>

#define DIM 256
#define MAXS 20000
#define S_PAD 20096   // 157 * 128 GEMM padding; tail rows stay zero

// ---------------- scratch (__device__ globals; zero-initialized at load) ----
__device__ __nv_bfloat16 g_pooled_hi[(size_t)S_PAD * DIM];
__device__ __nv_bfloat16 g_pooled_lo[(size_t)S_PAD * DIM];
__device__ float g_gsum[MAXS];
__device__ __nv_bfloat16 g_wmT_hi[DIM * DIM];   // Wm^T: [n][k]
__device__ __nv_bfloat16 g_wmT_lo[DIM * DIM];
__device__ int g_seg_start[MAXS + 1];

// ---------------- helpers ---------------------------------------------------
__device__ __forceinline__ uint32_t smem_u32(const void* p) {
    uint32_t a;
    asm("{ .reg .u64 t; cvta.to.shared.u64 t, %1; cvt.u32.u64 %0, t; }"
        : "=r"(a) : "l"(p));
    return a;
}
__device__ __forceinline__ void ldm_x4(uint32_t* r, uint32_t addr) {
    asm volatile("ldmatrix.sync.aligned.m8n8.x4.shared.b16 {%0,%1,%2,%3}, [%4];"
                 : "=r"(r[0]), "=r"(r[1]), "=r"(r[2]), "=r"(r[3]) : "r"(addr));
}
__device__ __forceinline__ void mma_bf16(float* c, const uint32_t* a, const uint32_t* b) {
    asm volatile("mma.sync.aligned.m16n8k16.row.col.f32.bf16.bf16.f32 "
                 "{%0,%1,%2,%3}, {%4,%5,%6,%7}, {%8,%9}, {%0,%1,%2,%3};"
                 : "+f"(c[0]), "+f"(c[1]), "+f"(c[2]), "+f"(c[3])
                 : "r"(a[0]), "r"(a[1]), "r"(a[2]), "r"(a[3]), "r"(b[0]), "r"(b[1]));
}
__device__ __forceinline__ uint32_t pack_bf2(float a, float b) {
    __nv_bfloat162 h = __floats2bfloat162_rn(a, b);
    return *(uint32_t*)&h;
}
__device__ __forceinline__ void pf_l2(const void* p) {
    asm volatile("prefetch.global.L2 [%0];" :: "l"(p));
}

// ---------------------------------------------------------------------------
// Kernel 0: segment boundary scatter (blocks [0, nScatter)) + Wm^T bf16 hi/lo
// via smem 32x32 tile transpose (last 64 blocks). The old direct transpose
// did 2-byte stores at 512B stride (65K partial-line wavefronts, twice);
// the tiled version loads coalesced fp32 rows and writes coalesced 64B bf16
// rows -> bounds_prep 7.4us -> ~3us.
// ---------------------------------------------------------------------------
__global__ void __launch_bounds__(256) bounds_prep_kernel(
    const int* __restrict__ index, const float* __restrict__ Wm,
    int N, int S, int nScatter)
{
    if ((int)blockIdx.x < nScatter) {
        int i0 = (blockIdx.x * 256 + threadIdx.x) * 4;
        if (i0 < N) {
            int prev = (i0 == 0) ? -1 : __ldg(index + i0 - 1);
            #pragma unroll
            for (int j = 0; j < 4; j++) {
                int i = i0 + j;
                if (i < N) {
                    int b = __ldg(index + i);
                    for (int s = prev + 1; s <= b; s++) g_seg_start[s] = i;
                    prev = b;
                    if (i == N - 1)
                        for (int s = b + 1; s <= S; s++) g_seg_start[s] = N;
                }
            }
        }
        return;
    }

    // Wm transpose: 64 tiles of 32x32 (DIM/32 = 8 per side)
    __shared__ float tile[32][33];
    int t = threadIdx.x;
    int tix = (int)blockIdx.x - nScatter;   // 0..63
    int ti = tix >> 3;                       // k-tile
    int tj = tix & 7;                        // n-tile
    int lr = t >> 5;                         // 0..7
    int lc = t & 31;                         // 0..31

    #pragma unroll
    for (int p = 0; p < 4; p++) {
        int row = p * 8 + lr;                // k-local
        tile[row][lc] = Wm[(size_t)(ti * 32 + row) * DIM + tj * 32 + lc];
    }
    __syncthreads();
    #pragma unroll
    for (int p = 0; p < 4; p++) {
        int row = p * 8 + lr;                // n-local
        float v = tile[lc][row];
        __nv_bfloat16 hi = __float2bfloat16(v);
        size_t dst = (size_t)(tj * 32 + row) * DIM + ti * 32 + lc;
        g_wmT_hi[dst] = hi;
        g_wmT_lo[dst] = __float2bfloat16(v - __bfloat162float(hi));
    }
}

// ---------------------------------------------------------------------------
// Kernel A: WARP-per-segment single-pass softmax pooling, L2 prefetch @8 rows.
// EXACT R7 body (measured-best 139.7us total): unroll-4, one
// prefetch.global.L2 per iteration covering the 4 rows two iterations ahead,
// __powf/__expf gate math, no smem, no block syncs.
// Softmax max-subtraction cancels algebraically (gate ~ N(0,1), exp safe).
// ---------------------------------------------------------------------------
__global__ void __launch_bounds__(256) seg_pool_kernel(
    const float* __restrict__ x,
    const float* __restrict__ weights,
    const float* __restrict__ Wg,
    const float* __restrict__ pptr,
    int N, int S)
{
    int w = threadIdx.x >> 5, lane = threadIdx.x & 31;
    int s = blockIdx.x * 8 + w;
    if (s >= S) return;

    int n0 = g_seg_start[s];
    int cnt = g_seg_start[s + 1] - n0;
    float pval = pptr[0];

    size_t po = (size_t)s * DIM;
    if (cnt == 0) {
        *(uint2*)(g_pooled_hi + po + 4 * lane)       = make_uint2(0, 0);
        *(uint2*)(g_pooled_hi + po + 128 + 4 * lane) = make_uint2(0, 0);
        *(uint2*)(g_pooled_lo + po + 4 * lane)       = make_uint2(0, 0);
        *(uint2*)(g_pooled_lo + po + 128 + 4 * lane) = make_uint2(0, 0);
        if (lane == 0) g_gsum[s] = 0.f;
        return;
    }

    const float4* Wg4 = (const float4*)Wg;
    float4 wg0 = __ldg(Wg4 + lane);
    float4 wg1 = __ldg(Wg4 + lane + 32);

    int pf_row_off = lane >> 3;          // 0..3
    int pf_col     = (lane & 7) * 32;    // float offset of a 128B line

    float acc[8] = {};
    float denom = 0.f;

    int i = 0;
    for (; i + 4 <= cnt; i += 4) {
        const float4* x0 = (const float4*)(x + (size_t)(n0 + i) * DIM);
        const float4* x1 = (const float4*)(x + (size_t)(n0 + i + 1) * DIM);
        const float4* x2 = (const float4*)(x + (size_t)(n0 + i + 2) * DIM);
        const float4* x3 = (const float4*)(x + (size_t)(n0 + i + 3) * DIM);
        float4 a0 = x0[lane], a1 = x0[lane + 32];
        float4 b0 = x1[lane], b1 = x1[lane + 32];
        float4 c0 = x2[lane], c1 = x2[lane + 32];
        float4 d0 = x3[lane], d1 = x3[lane + 32];
        float wt0 = __ldg(weights + n0 + i);
        float wt1 = __ldg(weights + n0 + i + 1);
        float wt2 = __ldg(weights + n0 + i + 2);
        float wt3 = __ldg(weights + n0 + i + 3);

        // prefetch 4 rows, 8 ahead (2 iterations); clamp only to N
        int pr = n0 + i + 8 + pf_row_off;
        pr = (pr < N) ? pr : (N - 1);
        pf_l2(x + (size_t)pr * DIM + pf_col);

        float g0 = a0.x * wg0.x + a0.y * wg0.y + a0.z * wg0.z + a0.w * wg0.w
                 + a1.x * wg1.x + a1.y * wg1.y + a1.z * wg1.z + a1.w * wg1.w;
        float g1 = b0.x * wg0.x + b0.y * wg0.y + b0.z * wg0.z + b0.w * wg0.w
                 + b1.x * wg1.x + b1.y * wg1.y + b1.z * wg1.z + b1.w * wg1.w;
        float g2 = c0.x * wg0.x + c0.y * wg0.y + c0.z * wg0.z + c0.w * wg0.w
                 + c1.x * wg1.x + c1.y * wg1.y + c1.z * wg1.z + c1.w * wg1.w;
        float g3 = d0.x * wg0.x + d0.y * wg0.y + d0.z * wg0.z + d0.w * wg0.w
                 + d1.x * wg1.x + d1.y * wg1.y + d1.z * wg1.z + d1.w * wg1.w;
        #pragma unroll
        for (int o = 16; o; o >>= 1) {
            g0 += __shfl_xor_sync(0xFFFFFFFFu, g0, o);
            g1 += __shfl_xor_sync(0xFFFFFFFFu, g1, o);
            g2 += __shfl_xor_sync(0xFFFFFFFFu, g2, o);
            g3 += __shfl_xor_sync(0xFFFFFFFFu, g3, o);
        }
        float gv0 = __powf(wt0, pval) * __expf(g0);
        float gv1 = __powf(wt1, pval) * __expf(g1);
        float gv2 = __powf(wt2, pval) * __expf(g2);
        float gv3 = __powf(wt3, pval) * __expf(g3);
        denom += (gv0 + gv1) + (gv2 + gv3);
        acc[0] += gv0 * a0.x + gv1 * b0.x + gv2 * c0.x + gv3 * d0.x;
        acc[1] += gv0 * a0.y + gv1 * b0.y + gv2 * c0.y + gv3 * d0.y;
        acc[2] += gv0 * a0.z + gv1 * b0.z + gv2 * c0.z + gv3 * d0.z;
        acc[3] += gv0 * a0.w + gv1 * b0.w + gv2 * c0.w + gv3 * d0.w;
        acc[4] += gv0 * a1.x + gv1 * b1.x + gv2 * c1.x + gv3 * d1.x;
        acc[5] += gv0 * a1.y + gv1 * b1.y + gv2 * c1.y + gv3 * d1.y;
        acc[6] += gv0 * a1.z + gv1 * b1.z + gv2 * c1.z + gv3 * d1.z;
        acc[7] += gv0 * a1.w + gv1 * b1.w + gv2 * c1.w + gv3 * d1.w;
    }
    for (; i < cnt; i++) {
        const float4* xr = (const float4*)(x + (size_t)(n0 + i) * DIM);
        float4 a0 = xr[lane], a1 = xr[lane + 32];
        float wt = __ldg(weights + n0 + i);
        float g = a0.x * wg0.x + a0.y * wg0.y + a0.z * wg0.z + a0.w * wg0.w
                + a1.x * wg1.x + a1.y * wg1.y + a1.z * wg1.z + a1.w * wg1.w;
        #pragma unroll
        for (int o = 16; o; o >>= 1) g += __shfl_xor_sync(0xFFFFFFFFu, g, o);
        float gv = __powf(wt, pval) * __expf(g);
        denom += gv;
        acc[0] += gv * a0.x; acc[1] += gv * a0.y;
        acc[2] += gv * a0.z; acc[3] += gv * a0.w;
        acc[4] += gv * a1.x; acc[5] += gv * a1.y;
        acc[6] += gv * a1.z; acc[7] += gv * a1.w;
    }

    float scale = 1.f / (denom + 1e-10f);
    float v[8], hi[8], lo[8];
    #pragma unroll
    for (int j = 0; j < 8; j++) {
        v[j] = acc[j] * scale;
        hi[j] = __bfloat162float(__float2bfloat16(v[j]));
        lo[j] = v[j] - hi[j];
    }
    *(uint2*)(g_pooled_hi + po + 4 * lane) =
        make_uint2(pack_bf2(hi[0], hi[1]), pack_bf2(hi[2], hi[3]));
    *(uint2*)(g_pooled_hi + po + 128 + 4 * lane) =
        make_uint2(pack_bf2(hi[4], hi[5]), pack_bf2(hi[6], hi[7]));
    *(uint2*)(g_pooled_lo + po + 4 * lane) =
        make_uint2(pack_bf2(lo[0], lo[1]), pack_bf2(lo[2], lo[3]));
    *(uint2*)(g_pooled_lo + po + 128 + 4 * lane) =
        make_uint2(pack_bf2(lo[4], lo[5]), pack_bf2(lo[6], lo[7]));
    if (lane == 0) g_gsum[s] = denom * scale;
}

// ---------------------------------------------------------------------------
// Kernel B: mma.sync bf16 split GEMM — static-smem version (measured good).
// out[S,256] = pooled@Wm + gsum*bm ≈ (Ahi Bhi + Ahi Blo + Alo Bhi), fp32 acc.
// ---------------------------------------------------------------------------
#define KPAD 40

__global__ void __launch_bounds__(256) out_gemm_mma_kernel(
    const float* __restrict__ bm, float* __restrict__ out, int S)
{
    __shared__ __nv_bfloat16 sAh[128 * KPAD];
    __shared__ __nv_bfloat16 sAl[128 * KPAD];
    __shared__ __nv_bfloat16 sBh[128 * KPAD];
    __shared__ __nv_bfloat16 sBl[128 * KPAD];

    int tid = threadIdx.x, wid = tid >> 5, lane = tid & 31;
    int wm = wid & 3, wn = wid >> 2;
    int m0 = blockIdx.x * 128;
    int nh = blockIdx.y * 128;

    uint32_t uAh = smem_u32(sAh), uAl = smem_u32(sAl);
    uint32_t uBh = smem_u32(sBh), uBl = smem_u32(sBl);

    uint32_t a_row = wm * 32 + (lane & 15);
    uint32_t a_k8  = (lane >> 4) * 8;
    uint32_t b_row = wn * 64 + (lane >> 4) * 8 + (lane & 7);
    uint32_t b_k8  = ((lane >> 3) & 1) * 8;

    float acc[2][8][4];
    #pragma unroll
    for (int i = 0; i < 2; i++)
        #pragma unroll
        for (int j = 0; j < 8; j++)
            #pragma unroll
            for (int q = 0; q < 4; q++) acc[i][j][q] = 0.f;

    int r_ld[2], q_ld[2];
    #pragma unroll
    for (int i = 0; i < 2; i++) {
        int it = tid * 2 + i;
        r_ld[i] = it >> 2;
        q_ld[i] = it & 3;
    }

    for (int c = 0; c < 8; c++) {
        int k0 = c * 32;
        #pragma unroll
        for (int i = 0; i < 2; i++) {
            int r = r_ld[i], q = q_ld[i];
            uint32_t doff = (uint32_t)(r * KPAD + q * 8);
            size_t asrc = (size_t)(m0 + r) * DIM + k0 + q * 8;
            size_t bsrc = (size_t)(nh + r) * DIM + k0 + q * 8;
            *(uint4*)(sAh + doff) = *(const uint4*)(g_pooled_hi + asrc);
            *(uint4*)(sAl + doff) = *(const uint4*)(g_pooled_lo + asrc);
            *(uint4*)(sBh + doff) = *(const uint4*)(g_wmT_hi + bsrc);
            *(uint4*)(sBl + doff) = *(const uint4*)(g_wmT_lo + bsrc);
        }
        __syncthreads();

        #pragma unroll
        for (int kk = 0; kk < 32; kk += 16) {
            uint32_t ah[2][4], al[2][4];
            #pragma unroll
            for (int mt = 0; mt < 2; mt++) {
                uint32_t off = ((a_row + mt * 16) * KPAD + kk + a_k8) * 2;
                ldm_x4(ah[mt], uAh + off);
                ldm_x4(al[mt], uAl + off);
            }
            uint32_t bh[4][4], bl[4][4];
            #pragma unroll
            for (int nt = 0; nt < 4; nt++) {
                uint32_t off = ((b_row + nt * 16) * KPAD + kk + b_k8) * 2;
                ldm_x4(bh[nt], uBh + off);
                ldm_x4(bl[nt], uBl + off);
            }
            #pragma unroll
            for (int mt = 0; mt < 2; mt++)
                #pragma unroll
                for (int nt = 0; nt < 8; nt++) {
                    const uint32_t* pbh = &bh[nt >> 1][(nt & 1) * 2];
                    const uint32_t* pbl = &bl[nt >> 1][(nt & 1) * 2];
                    mma_bf16(acc[mt][nt], ah[mt], pbh);
                    mma_bf16(acc[mt][nt], ah[mt], pbl);
                    mma_bf16(acc[mt][nt], al[mt], pbh);
                }
        }
        __syncthreads();
    }

    #pragma unroll
    for (int mt = 0; mt < 2; mt++) {
        int r0 = m0 + wm * 32 + mt * 16 + (lane >> 2);
        int r1 = r0 + 8;
        float gs0 = (r0 < S) ? g_gsum[r0] : 0.f;
        float gs1 = (r1 < S) ? g_gsum[r1] : 0.f;
        #pragma unroll
        for (int nt = 0; nt < 8; nt++) {
            int col = nh + wn * 64 + nt * 8 + (lane & 3) * 2;
            float2 bm2 = *(const float2*)(bm + col);
            if (r0 < S) {
                float2 v = make_float2(acc[mt][nt][0] + gs0 * bm2.x,
                                       acc[mt][nt][1] + gs0 * bm2.y);
                *(float2*)(out + (size_t)r0 * DIM + col) = v;
            }
            if (r1 < S) {
                float2 v = make_float2(acc[mt][nt][2] + gs1 * bm2.x,
                                       acc[mt][nt][3] + gs1 * bm2.y);
                *(float2*)(out + (size_t)r1 * DIM + col) = v;
            }
        }
    }
}

// ---------------------------------------------------------------------------
// Launch. Inputs: x, weights, Wg, bg, Wm, bm, p, index, num_segments
// bg cancels in the segment softmax.
// ---------------------------------------------------------------------------
extern "C" void kernel_launch(void* const* d_in, const int* in_sizes, int n_in,
                              void* d_out, int out_size) {
    const float* x       = (const float*)d_in[0];
    const float* weights = (const float*)d_in[1];
    const float* Wg      = (const float*)d_in[2];
    const float* Wm      = (const float*)d_in[4];
    const float* bm      = (const float*)d_in[5];
    const float* p       = (const float*)d_in[6];
    const int*   index   = (const int*)d_in[7];

    int N = in_sizes[0] / DIM;
    int S = out_size / DIM;
    float* out = (float*)d_out;

    int nScatter = (N + 1023) / 1024;
    bounds_prep_kernel<<<nScatter + 64, 256>>>(index, Wm, N, S, nScatter);

    seg_pool_kernel<<<(S + 7) / 8, 256>>>(x, weights, Wg, p, N, S);

    dim3 grid((S + 127) / 128, 2);
    out_gemm_mma_kernel<<<grid, 256>>>(bm, out, S);
}

// round 17
// speedup vs baseline: 1.1594x; 1.0257x over previous
#include <cuda_runtime.h>
#include <cuda_bf16.h>
#include <cstdint>

#define DIM 256
#define MAXS 20000
#define S_PAD 20096   // 157 * 128 GEMM padding; tail rows stay zero

// ---------------- scratch (__device__ globals; zero-initialized at load) ----
__device__ __nv_bfloat16 g_pooled_hi[(size_t)S_PAD * DIM];
__device__ __nv_bfloat16 g_pooled_lo[(size_t)S_PAD * DIM];
__device__ float g_gsum[MAXS];
__device__ __nv_bfloat16 g_wmT_hi[DIM * DIM];   // Wm^T: [n][k]
__device__ __nv_bfloat16 g_wmT_lo[DIM * DIM];
__device__ int g_seg_start[MAXS + 1];

// ---------------- helpers ---------------------------------------------------
__device__ __forceinline__ uint32_t smem_u32(const void* p) {
    uint32_t a;
    asm("{ .reg .u64 t; cvta.to.shared.u64 t, %1; cvt.u32.u64 %0, t; }"
        : "=r"(a) : "l"(p));
    return a;
}
__device__ __forceinline__ void ldm_x4(uint32_t* r, uint32_t addr) {
    asm volatile("ldmatrix.sync.aligned.m8n8.x4.shared.b16 {%0,%1,%2,%3}, [%4];"
                 : "=r"(r[0]), "=r"(r[1]), "=r"(r[2]), "=r"(r[3]) : "r"(addr));
}
__device__ __forceinline__ void mma_bf16(float* c, const uint32_t* a, const uint32_t* b) {
    asm volatile("mma.sync.aligned.m16n8k16.row.col.f32.bf16.bf16.f32 "
                 "{%0,%1,%2,%3}, {%4,%5,%6,%7}, {%8,%9}, {%0,%1,%2,%3};"
                 : "+f"(c[0]), "+f"(c[1]), "+f"(c[2]), "+f"(c[3])
                 : "r"(a[0]), "r"(a[1]), "r"(a[2]), "r"(a[3]), "r"(b[0]), "r"(b[1]));
}
__device__ __forceinline__ uint32_t pack_bf2(float a, float b) {
    __nv_bfloat162 h = __floats2bfloat162_rn(a, b);
    return *(uint32_t*)&h;
}
__device__ __forceinline__ void pf_l2(const void* p) {
    asm volatile("prefetch.global.L2 [%0];" :: "l"(p));
}
__device__ __forceinline__ void cp16(uint32_t dst, const void* src) {
    asm volatile("cp.async.cg.shared.global [%0], [%1], 16;" :: "r"(dst), "l"(src));
}

// ---------------------------------------------------------------------------
// Kernel 0: segment boundary scatter (blocks [0, nScatter)) + Wm^T bf16 hi/lo
// via smem 32x32 tile transpose (last 64 blocks). Measured 5.0us.
// ---------------------------------------------------------------------------
__global__ void __launch_bounds__(256) bounds_prep_kernel(
    const int* __restrict__ index, const float* __restrict__ Wm,
    int N, int S, int nScatter)
{
    if ((int)blockIdx.x < nScatter) {
        int i0 = (blockIdx.x * 256 + threadIdx.x) * 4;
        if (i0 < N) {
            int prev = (i0 == 0) ? -1 : __ldg(index + i0 - 1);
            #pragma unroll
            for (int j = 0; j < 4; j++) {
                int i = i0 + j;
                if (i < N) {
                    int b = __ldg(index + i);
                    for (int s = prev + 1; s <= b; s++) g_seg_start[s] = i;
                    prev = b;
                    if (i == N - 1)
                        for (int s = b + 1; s <= S; s++) g_seg_start[s] = N;
                }
            }
        }
        return;
    }

    __shared__ float tile[32][33];
    int t = threadIdx.x;
    int tix = (int)blockIdx.x - nScatter;   // 0..63
    int ti = tix >> 3;                       // k-tile
    int tj = tix & 7;                        // n-tile
    int lr = t >> 5;                         // 0..7
    int lc = t & 31;                         // 0..31

    #pragma unroll
    for (int p = 0; p < 4; p++) {
        int row = p * 8 + lr;
        tile[row][lc] = Wm[(size_t)(ti * 32 + row) * DIM + tj * 32 + lc];
    }
    __syncthreads();
    #pragma unroll
    for (int p = 0; p < 4; p++) {
        int row = p * 8 + lr;
        float v = tile[lc][row];
        __nv_bfloat16 hi = __float2bfloat16(v);
        size_t dst = (size_t)(tj * 32 + row) * DIM + ti * 32 + lc;
        g_wmT_hi[dst] = hi;
        g_wmT_lo[dst] = __float2bfloat16(v - __bfloat162float(hi));
    }
}

// ---------------------------------------------------------------------------
// Kernel A: WARP-per-segment single-pass softmax pooling (EXACT R7/R16 body,
// measured best): unroll-4, distance-8 prefetch.global.L2, __powf/__expf.
// Softmax max-subtraction cancels algebraically (gate ~ N(0,1), exp safe).
// ---------------------------------------------------------------------------
__global__ void __launch_bounds__(256) seg_pool_kernel(
    const float* __restrict__ x,
    const float* __restrict__ weights,
    const float* __restrict__ Wg,
    const float* __restrict__ pptr,
    int N, int S)
{
    int w = threadIdx.x >> 5, lane = threadIdx.x & 31;
    int s = blockIdx.x * 8 + w;
    if (s >= S) return;

    int n0 = g_seg_start[s];
    int cnt = g_seg_start[s + 1] - n0;
    float pval = pptr[0];

    size_t po = (size_t)s * DIM;
    if (cnt == 0) {
        *(uint2*)(g_pooled_hi + po + 4 * lane)       = make_uint2(0, 0);
        *(uint2*)(g_pooled_hi + po + 128 + 4 * lane) = make_uint2(0, 0);
        *(uint2*)(g_pooled_lo + po + 4 * lane)       = make_uint2(0, 0);
        *(uint2*)(g_pooled_lo + po + 128 + 4 * lane) = make_uint2(0, 0);
        if (lane == 0) g_gsum[s] = 0.f;
        return;
    }

    const float4* Wg4 = (const float4*)Wg;
    float4 wg0 = __ldg(Wg4 + lane);
    float4 wg1 = __ldg(Wg4 + lane + 32);

    int pf_row_off = lane >> 3;          // 0..3
    int pf_col     = (lane & 7) * 32;    // float offset of a 128B line

    float acc[8] = {};
    float denom = 0.f;

    int i = 0;
    for (; i + 4 <= cnt; i += 4) {
        const float4* x0 = (const float4*)(x + (size_t)(n0 + i) * DIM);
        const float4* x1 = (const float4*)(x + (size_t)(n0 + i + 1) * DIM);
        const float4* x2 = (const float4*)(x + (size_t)(n0 + i + 2) * DIM);
        const float4* x3 = (const float4*)(x + (size_t)(n0 + i + 3) * DIM);
        float4 a0 = x0[lane], a1 = x0[lane + 32];
        float4 b0 = x1[lane], b1 = x1[lane + 32];
        float4 c0 = x2[lane], c1 = x2[lane + 32];
        float4 d0 = x3[lane], d1 = x3[lane + 32];
        float wt0 = __ldg(weights + n0 + i);
        float wt1 = __ldg(weights + n0 + i + 1);
        float wt2 = __ldg(weights + n0 + i + 2);
        float wt3 = __ldg(weights + n0 + i + 3);

        int pr = n0 + i + 8 + pf_row_off;
        pr = (pr < N) ? pr : (N - 1);
        pf_l2(x + (size_t)pr * DIM + pf_col);

        float g0 = a0.x * wg0.x + a0.y * wg0.y + a0.z * wg0.z + a0.w * wg0.w
                 + a1.x * wg1.x + a1.y * wg1.y + a1.z * wg1.z + a1.w * wg1.w;
        float g1 = b0.x * wg0.x + b0.y * wg0.y + b0.z * wg0.z + b0.w * wg0.w
                 + b1.x * wg1.x + b1.y * wg1.y + b1.z * wg1.z + b1.w * wg1.w;
        float g2 = c0.x * wg0.x + c0.y * wg0.y + c0.z * wg0.z + c0.w * wg0.w
                 + c1.x * wg1.x + c1.y * wg1.y + c1.z * wg1.z + c1.w * wg1.w;
        float g3 = d0.x * wg0.x + d0.y * wg0.y + d0.z * wg0.z + d0.w * wg0.w
                 + d1.x * wg1.x + d1.y * wg1.y + d1.z * wg1.z + d1.w * wg1.w;
        #pragma unroll
        for (int o = 16; o; o >>= 1) {
            g0 += __shfl_xor_sync(0xFFFFFFFFu, g0, o);
            g1 += __shfl_xor_sync(0xFFFFFFFFu, g1, o);
            g2 += __shfl_xor_sync(0xFFFFFFFFu, g2, o);
            g3 += __shfl_xor_sync(0xFFFFFFFFu, g3, o);
        }
        float gv0 = __powf(wt0, pval) * __expf(g0);
        float gv1 = __powf(wt1, pval) * __expf(g1);
        float gv2 = __powf(wt2, pval) * __expf(g2);
        float gv3 = __powf(wt3, pval) * __expf(g3);
        denom += (gv0 + gv1) + (gv2 + gv3);
        acc[0] += gv0 * a0.x + gv1 * b0.x + gv2 * c0.x + gv3 * d0.x;
        acc[1] += gv0 * a0.y + gv1 * b0.y + gv2 * c0.y + gv3 * d0.y;
        acc[2] += gv0 * a0.z + gv1 * b0.z + gv2 * c0.z + gv3 * d0.z;
        acc[3] += gv0 * a0.w + gv1 * b0.w + gv2 * c0.w + gv3 * d0.w;
        acc[4] += gv0 * a1.x + gv1 * b1.x + gv2 * c1.x + gv3 * d1.x;
        acc[5] += gv0 * a1.y + gv1 * b1.y + gv2 * c1.y + gv3 * d1.y;
        acc[6] += gv0 * a1.z + gv1 * b1.z + gv2 * c1.z + gv3 * d1.z;
        acc[7] += gv0 * a1.w + gv1 * b1.w + gv2 * c1.w + gv3 * d1.w;
    }
    for (; i < cnt; i++) {
        const float4* xr = (const float4*)(x + (size_t)(n0 + i) * DIM);
        float4 a0 = xr[lane], a1 = xr[lane + 32];
        float wt = __ldg(weights + n0 + i);
        float g = a0.x * wg0.x + a0.y * wg0.y + a0.z * wg0.z + a0.w * wg0.w
                + a1.x * wg1.x + a1.y * wg1.y + a1.z * wg1.z + a1.w * wg1.w;
        #pragma unroll
        for (int o = 16; o; o >>= 1) g += __shfl_xor_sync(0xFFFFFFFFu, g, o);
        float gv = __powf(wt, pval) * __expf(g);
        denom += gv;
        acc[0] += gv * a0.x; acc[1] += gv * a0.y;
        acc[2] += gv * a0.z; acc[3] += gv * a0.w;
        acc[4] += gv * a1.x; acc[5] += gv * a1.y;
        acc[6] += gv * a1.z; acc[7] += gv * a1.w;
    }

    float scale = 1.f / (denom + 1e-10f);
    float v[8], hi[8], lo[8];
    #pragma unroll
    for (int j = 0; j < 8; j++) {
        v[j] = acc[j] * scale;
        hi[j] = __bfloat162float(__float2bfloat16(v[j]));
        lo[j] = v[j] - hi[j];
    }
    *(uint2*)(g_pooled_hi + po + 4 * lane) =
        make_uint2(pack_bf2(hi[0], hi[1]), pack_bf2(hi[2], hi[3]));
    *(uint2*)(g_pooled_hi + po + 128 + 4 * lane) =
        make_uint2(pack_bf2(hi[4], hi[5]), pack_bf2(hi[6], hi[7]));
    *(uint2*)(g_pooled_lo + po + 4 * lane) =
        make_uint2(pack_bf2(lo[0], lo[1]), pack_bf2(lo[2], lo[3]));
    *(uint2*)(g_pooled_lo + po + 128 + 4 * lane) =
        make_uint2(pack_bf2(lo[4], lo[5]), pack_bf2(lo[6], lo[7]));
    if (lane == 0) g_gsum[s] = denom * scale;
}

// ---------------------------------------------------------------------------
// Kernel B: mma.sync bf16 split GEMM, cp.async 2-stage double-buffered
// (R5 version, correctness-proven; measured here in ISOLATION for the first
// time against the 137.7us static-smem baseline).
// out[S,256] = pooled@Wm + gsum*bm ≈ (Ahi Bhi + Ahi Blo + Alo Bhi), fp32 acc.
// ---------------------------------------------------------------------------
#define KPAD 40
#define MAT_BYTES (128 * KPAD * 2)          // 10240
#define STAGE_BYTES (4 * MAT_BYTES)         // 40960
#define GEMM_SMEM (2 * STAGE_BYTES)         // 81920

__global__ void __launch_bounds__(256) out_gemm_mma_kernel(
    const float* __restrict__ bm, float* __restrict__ out, int S)
{
    extern __shared__ char dsm[];
    uint32_t sb = smem_u32(dsm);

    int tid = threadIdx.x, wid = tid >> 5, lane = tid & 31;
    int wm = wid & 3, wn = wid >> 2;
    int m0 = blockIdx.x * 128;
    int nh = blockIdx.y * 128;

    uint32_t a_row = wm * 32 + (lane & 15);
    uint32_t a_k8  = (lane >> 4) * 8;
    uint32_t b_row = wn * 64 + (lane >> 4) * 8 + (lane & 7);
    uint32_t b_k8  = ((lane >> 3) & 1) * 8;

    float acc[2][8][4];
    #pragma unroll
    for (int i = 0; i < 2; i++)
        #pragma unroll
        for (int j = 0; j < 8; j++)
            #pragma unroll
            for (int q = 0; q < 4; q++) acc[i][j][q] = 0.f;

    int r_ld[2], q_ld[2];
    #pragma unroll
    for (int i = 0; i < 2; i++) {
        int it = tid * 2 + i;
        r_ld[i] = it >> 2;
        q_ld[i] = it & 3;
    }

    auto issue_stage = [&](int c, int st) {
        uint32_t base = sb + st * STAGE_BYTES;
        int k0 = c * 32;
        #pragma unroll
        for (int i = 0; i < 2; i++) {
            int r = r_ld[i], q = q_ld[i];
            uint32_t doff = (uint32_t)(r * KPAD + q * 8) * 2;
            size_t asrc = (size_t)(m0 + r) * DIM + k0 + q * 8;
            size_t bsrc = (size_t)(nh + r) * DIM + k0 + q * 8;
            cp16(base + 0 * MAT_BYTES + doff, g_pooled_hi + asrc);
            cp16(base + 1 * MAT_BYTES + doff, g_pooled_lo + asrc);
            cp16(base + 2 * MAT_BYTES + doff, g_wmT_hi + bsrc);
            cp16(base + 3 * MAT_BYTES + doff, g_wmT_lo + bsrc);
        }
        asm volatile("cp.async.commit_group;" ::: "memory");
    };

    issue_stage(0, 0);

    for (int c = 0; c < 8; c++) {
        if (c < 7) issue_stage(c + 1, (c + 1) & 1);
        if (c < 7) asm volatile("cp.async.wait_group 1;" ::: "memory");
        else       asm volatile("cp.async.wait_group 0;" ::: "memory");
        __syncthreads();

        uint32_t base = sb + (c & 1) * STAGE_BYTES;
        uint32_t uAh = base, uAl = base + MAT_BYTES;
        uint32_t uBh = base + 2 * MAT_BYTES, uBl = base + 3 * MAT_BYTES;

        #pragma unroll
        for (int kk = 0; kk < 32; kk += 16) {
            uint32_t ah[2][4], al[2][4];
            #pragma unroll
            for (int mt = 0; mt < 2; mt++) {
                uint32_t off = ((a_row + mt * 16) * KPAD + kk + a_k8) * 2;
                ldm_x4(ah[mt], uAh + off);
                ldm_x4(al[mt], uAl + off);
            }
            uint32_t bh[4][4], bl[4][4];
            #pragma unroll
            for (int nt = 0; nt < 4; nt++) {
                uint32_t off = ((b_row + nt * 16) * KPAD + kk + b_k8) * 2;
                ldm_x4(bh[nt], uBh + off);
                ldm_x4(bl[nt], uBl + off);
            }
            #pragma unroll
            for (int mt = 0; mt < 2; mt++)
                #pragma unroll
                for (int nt = 0; nt < 8; nt++) {
                    const uint32_t* pbh = &bh[nt >> 1][(nt & 1) * 2];
                    const uint32_t* pbl = &bl[nt >> 1][(nt & 1) * 2];
                    mma_bf16(acc[mt][nt], ah[mt], pbh);
                    mma_bf16(acc[mt][nt], ah[mt], pbl);
                    mma_bf16(acc[mt][nt], al[mt], pbh);
                }
        }
        __syncthreads();
    }

    #pragma unroll
    for (int mt = 0; mt < 2; mt++) {
        int r0 = m0 + wm * 32 + mt * 16 + (lane >> 2);
        int r1 = r0 + 8;
        float gs0 = (r0 < S) ? g_gsum[r0] : 0.f;
        float gs1 = (r1 < S) ? g_gsum[r1] : 0.f;
        #pragma unroll
        for (int nt = 0; nt < 8; nt++) {
            int col = nh + wn * 64 + nt * 8 + (lane & 3) * 2;
            float2 bm2 = *(const float2*)(bm + col);
            if (r0 < S) {
                float2 v = make_float2(acc[mt][nt][0] + gs0 * bm2.x,
                                       acc[mt][nt][1] + gs0 * bm2.y);
                *(float2*)(out + (size_t)r0 * DIM + col) = v;
            }
            if (r1 < S) {
                float2 v = make_float2(acc[mt][nt][2] + gs1 * bm2.x,
                                       acc[mt][nt][3] + gs1 * bm2.y);
                *(float2*)(out + (size_t)r1 * DIM + col) = v;
            }
        }
    }
}

// ---------------------------------------------------------------------------
// Launch. Inputs: x, weights, Wg, bg, Wm, bm, p, index, num_segments
// bg cancels in the segment softmax.
// ---------------------------------------------------------------------------
extern "C" void kernel_launch(void* const* d_in, const int* in_sizes, int n_in,
                              void* d_out, int out_size) {
    const float* x       = (const float*)d_in[0];
    const float* weights = (const float*)d_in[1];
    const float* Wg      = (const float*)d_in[2];
    const float* Wm      = (const float*)d_in[4];
    const float* bm      = (const float*)d_in[5];
    const float* p       = (const float*)d_in[6];
    const int*   index   = (const int*)d_in[7];

    int N = in_sizes[0] / DIM;
    int S = out_size / DIM;
    float* out = (float*)d_out;

    cudaFuncSetAttribute(out_gemm_mma_kernel,
                         cudaFuncAttributeMaxDynamicSharedMemorySize, GEMM_SMEM);

    int nScatter = (N + 1023) / 1024;
    bounds_prep_kernel<<<nScatter + 64, 256>>>(index, Wm, N, S, nScatter);

    seg_pool_kernel<<<(S + 7) / 8, 256>>>(x, weights, Wg, p, N, S);

    dim3 grid((S + 127) / 128, 2);
    out_gemm_mma_kernel<<<grid, 256, GEMM_SMEM>>>(bm, out, S);
}